// round 17
// baseline (speedup 1.0000x reference)
#include <cuda_runtime.h>
#include <math.h>

constexpr int NDIM  = 80;
constexpr int BATCH = 64;
constexpr int SEQ   = 1000;
constexpr int KST   = 12;
constexpr int NBK   = BATCH * KST;   // 768
constexpr int ST    = 64;            // samples per block (kernel B)
constexpr int KPB   = 3;             // k's per block
constexpr int KGRP  = KST / KPB;     // 4
constexpr int MST   = 84;            // msh row stride
constexpr int DST2  = 136;           // ds row stride (64 samples x2 dup + pad)
constexpr int RSP   = 68;            // red row stride
constexpr int AST   = 84;            // chol A row stride

constexpr float LOG_2PI = 1.837877066409345339082f;
constexpr float EPS = 1e-5f;

__device__ float g_minvT[(size_t)NBK * NDIM * NDIM];  // [j][i] = X[i][j], dense
__device__ float g_logdet[NBK];
__device__ float g_negc[(size_t)NBK * NDIM];          // -L^-1*mu per (b,k)

typedef unsigned long long ull;
__device__ __forceinline__ ull fma2(ull a, ull b, ull c) {
    ull d; asm("fma.rn.f32x2 %0,%1,%2,%3;" : "=l"(d) : "l"(a), "l"(b), "l"(c)); return d;
}
__device__ __forceinline__ ull mul2(ull a, ull b) {
    ull d; asm("mul.rn.f32x2 %0,%1,%2;" : "=l"(d) : "l"(a), "l"(b)); return d;
}
__device__ __forceinline__ ull add2(ull a, ull b) {
    ull d; asm("add.rn.f32x2 %0,%1,%2;" : "=l"(d) : "l"(a), "l"(b)); return d;
}
__device__ __forceinline__ ull dup2(float x) {
    ull d; asm("mov.b64 %0,{%1,%1};" : "=l"(d) : "f"(x)); return d;
}
__device__ __forceinline__ float2 asf2(ull v) {
    float2 r; asm("mov.b64 {%0,%1},%2;" : "=f"(r.x), "=f"(r.y) : "l"(v)); return r;
}

// ---------------------------------------------------------------------------
// Kernel A (R9 verbatim): elimination (LDS.128 rank-1 updates), scale to L,
// logdet, sync-free triangular inverse into upper triangle, negc, dense store.
// ---------------------------------------------------------------------------
__global__ __launch_bounds__(96) void chol_inv_kernel(const float* __restrict__ sigma,
                                                      const float* __restrict__ mu) {
    __shared__ __align__(16) float A[NDIM * AST];      // 26.9 KB
    __shared__ __align__(16) float colbuf[NDIM + 4];
    __shared__ __align__(16) float rinv[NDIM];
    __shared__ float lbuf[NDIM];
    __shared__ float mush[NDIM];
    __shared__ float dinvsh;

    const int bk  = blockIdx.x;
    const int tid = threadIdx.x;
    const int i   = tid;
    const float* Sg = sigma + (size_t)bk * NDIM * NDIM;

    for (int idx = tid; idx < NDIM * NDIM; idx += 96) {
        int r = idx / NDIM, c = idx % NDIM;
        float v = Sg[idx];
        if (r == c) v += EPS;
        A[r * AST + c] = v;
    }
    __syncthreads();

    for (int k = 0; k < NDIM - 1; ++k) {
        if (tid < NDIM) colbuf[tid] = A[tid * AST + k];
        if (tid == 0) dinvsh = 1.0f / A[k * AST + k];
        __syncthreads();
        if (i > k && i < NDIM) {
            float nci = -colbuf[i] * dinvsh;
            ull  nc2 = dup2(nci);
            float* Ai = A + i * AST;
            int j = k + 1;
            for (; j <= i && (j & 3); ++j) Ai[j] = fmaf(nci, colbuf[j], Ai[j]);
            #pragma unroll 2
            for (; j + 3 <= i; j += 4) {
                ulonglong2 a2 = *reinterpret_cast<ulonglong2*>(Ai + j);
                ulonglong2 c2 = *reinterpret_cast<const ulonglong2*>(colbuf + j);
                a2.x = fma2(nc2, c2.x, a2.x);
                a2.y = fma2(nc2, c2.y, a2.y);
                *reinterpret_cast<ulonglong2*>(Ai + j) = a2;
            }
            for (; j <= i; ++j) Ai[j] = fmaf(nci, colbuf[j], Ai[j]);
        }
        __syncthreads();
    }

    if (tid < NDIM) {
        float d = A[tid * AST + tid];
        rinv[tid] = 1.0f / sqrtf(d);
        lbuf[tid] = logf(d);
    }
    if (tid < NDIM) mush[tid] = mu[(size_t)bk * NDIM + tid];
    __syncthreads();
    if (tid == 0) {
        float s = 0.0f;
        for (int j = 0; j < NDIM; ++j) s += lbuf[j];
        g_logdet[bk] = 0.5f * s;
    }
    if (i < NDIM) {
        float* Ai = A + i * AST;
        int k = 0;
        #pragma unroll 2
        for (; k + 3 <= i - 1; k += 4) {
            ulonglong2 a2 = *reinterpret_cast<ulonglong2*>(Ai + k);
            ulonglong2 r2 = *reinterpret_cast<const ulonglong2*>(rinv + k);
            a2.x = mul2(a2.x, r2.x);
            a2.y = mul2(a2.y, r2.y);
            *reinterpret_cast<ulonglong2*>(Ai + k) = a2;
        }
        for (; k <= i - 1; ++k) Ai[k] *= rinv[k];
    }
    __syncthreads();

    if (i > 0 && i < NDIM) {
        for (int jj = i - 1; jj >= 0; --jj) {
            float s0 = rinv[i] * A[i * AST + jj];
            float s1 = 0.f, s2 = 0.f, s3 = 0.f;
            int k = jj + 1;
            for (; k + 3 < i; k += 4) {
                s0 = fmaf(A[k * AST + i],     A[k * AST + jj],     s0);
                s1 = fmaf(A[(k+1) * AST + i], A[(k+1) * AST + jj], s1);
                s2 = fmaf(A[(k+2) * AST + i], A[(k+2) * AST + jj], s2);
                s3 = fmaf(A[(k+3) * AST + i], A[(k+3) * AST + jj], s3);
            }
            for (; k < i; ++k)
                s0 = fmaf(A[k * AST + i], A[k * AST + jj], s0);
            A[jj * AST + i] = -rinv[jj] * ((s0 + s1) + (s2 + s3));
        }
    }
    __syncthreads();

    if (i < NDIM) {
        float s = rinv[i] * mush[i];
        for (int jj = 0; jj < i; ++jj)
            s = fmaf(A[jj * AST + i], mush[jj], s);
        g_negc[(size_t)bk * NDIM + i] = -s;
    }

    float* out = g_minvT + (size_t)bk * NDIM * NDIM;
    for (int idx = tid; idx < NDIM * NDIM; idx += 96) {
        int j = idx / NDIM, c = idx % NDIM;
        float v;
        if (c > j)       v = A[j * AST + c];
        else if (c == j) v = rinv[c];
        else             v = 0.0f;
        out[idx] = v;
    }
}

// ---------------------------------------------------------------------------
// Kernel B: block = (s-tile of 64, k-group of 3, b). ds stores x DUPLICATED
// as f32x2 pairs ({v,v}) -> mainloop has ZERO dup MOVs. Warp (rg = ty>>1,
// half = ty&1): 16 rows {8rg..8rg+7} U {72-8rg..79-8rg}, 32 samples. Lane
// (rq = tx>>3, sq = tx&7): rows {8rg+2rq,+1} & {72-8rg+2rq,+1}, samples
// {4sq..4sq+3} of its half. Per A-j: 8 FFMA2 + 2 LDS.64(m) + 2 LDS.128(d).
// Work exactly uniform: 352 FFMA2 / lane. smem 72.1 KB -> 3 blocks/SM.
// ---------------------------------------------------------------------------
__global__ __launch_bounds__(320, 3) void ll_kernel(const float* __restrict__ x,
                                                    float* __restrict__ out) {
    extern __shared__ __align__(16) float sm[];
    float* msh  = sm;                       // [80][84]   MinvT [j][i]
    float* ds   = sm + NDIM * MST;          // [80][136]  x dup'd: [j][2s]
    float* red  = ds + NDIM * DST2;         // [5][68]
    float* ncsh = red + 5 * RSP;            // [84]

    const int tid = threadIdx.x;
    const int tx  = tid & 31;
    const int ty  = tid >> 5;               // warp 0..9
    const int s0  = blockIdx.x * ST;
    const int kg  = blockIdx.y;
    const int b   = blockIdx.z;

    int navail = SEQ - s0; if (navail > ST) navail = ST;
    const float* xb = x + ((size_t)b * SEQ + s0) * NDIM;

    // Stage x duplicated: ds[j][2s..2s+1] = {x[s][j], x[s][j]}
    for (int t = tid; t < (NDIM / 4) * ST; t += 320) {
        int n4 = t >> 6;                    // 0..19
        int s  = t & 63;                    // lanes dense in s
        float4 v = make_float4(0.f, 0.f, 0.f, 0.f);
        if (s < navail)
            v = *reinterpret_cast<const float4*>(xb + (size_t)s * NDIM + 4 * n4);
        *reinterpret_cast<ull*>(ds + (4 * n4 + 0) * DST2 + 2 * s) = dup2(v.x);
        *reinterpret_cast<ull*>(ds + (4 * n4 + 1) * DST2 + 2 * s) = dup2(v.y);
        *reinterpret_cast<ull*>(ds + (4 * n4 + 2) * DST2 + 2 * s) = dup2(v.z);
        *reinterpret_cast<ull*>(ds + (4 * n4 + 3) * DST2 + 2 * s) = dup2(v.w);
    }

    const int rg   = ty >> 1;               // row group 0..4
    const int half = ty & 1;                // sample half
    const int rq   = tx >> 3;               // row quad-pair 0..3
    const int sq   = tx & 7;                // sample group 0..7
    const int loff = 8 * rg + 2 * rq;       // low row pair base
    const int hoff = 72 - 16 * rg;          // high = low + hoff  [FIXED: was 64-16rg]
    const int jA   = 8 * rg + 8;            // all 16 warp rows active below jA
    const int jB   = 80 - 8 * rg;           // high rows only up to jB
    const int doff = 64 * half + 8 * sq;    // ds float offset of lane's samples

    for (int kk = 0; kk < KPB; ++kk) {
        const int k  = kg * KPB + kk;
        const int bk = b * KST + k;

        __syncthreads();                    // prior-k red reads / ds writes done
        const float* mv = g_minvT + (size_t)bk * NDIM * NDIM;
        for (int idx = tid; idx < NDIM * NDIM; idx += 320) {
            int j = idx / NDIM, i2 = idx - j * NDIM;
            msh[j * MST + i2] = __ldg(mv + idx);
        }
        if (tid < NDIM) ncsh[tid] = __ldg(g_negc + (size_t)bk * NDIM + tid);
        __syncthreads();

        ull accL[4], accH[4];
        #pragma unroll
        for (int s = 0; s < 4; ++s) { accL[s] = 0ULL; accH[s] = 0ULL; }

        const float* mp = msh + loff;
        const float* dp = ds + doff;

        #pragma unroll 2
        for (int j = 0; j < jA; ++j) {
            ull mlo = *reinterpret_cast<const ull*>(mp);
            ull mhi = *reinterpret_cast<const ull*>(mp + hoff);
            ulonglong2 dA = *reinterpret_cast<const ulonglong2*>(dp);
            ulonglong2 dB = *reinterpret_cast<const ulonglong2*>(dp + 4);
            accL[0] = fma2(mlo, dA.x, accL[0]);
            accL[1] = fma2(mlo, dA.y, accL[1]);
            accL[2] = fma2(mlo, dB.x, accL[2]);
            accL[3] = fma2(mlo, dB.y, accL[3]);
            accH[0] = fma2(mhi, dA.x, accH[0]);
            accH[1] = fma2(mhi, dA.y, accH[1]);
            accH[2] = fma2(mhi, dB.x, accH[2]);
            accH[3] = fma2(mhi, dB.y, accH[3]);
            mp += MST; dp += DST2;
        }
        #pragma unroll 4
        for (int j = jA; j < jB; ++j) {
            ull mhi = *reinterpret_cast<const ull*>(mp + hoff);
            ulonglong2 dA = *reinterpret_cast<const ulonglong2*>(dp);
            ulonglong2 dB = *reinterpret_cast<const ulonglong2*>(dp + 4);
            accH[0] = fma2(mhi, dA.x, accH[0]);
            accH[1] = fma2(mhi, dA.y, accH[1]);
            accH[2] = fma2(mhi, dB.x, accH[2]);
            accH[3] = fma2(mhi, dB.y, accH[3]);
            mp += MST; dp += DST2;
        }

        // Epilogue: z = acc - c (row pair), quad per sample, rq-reduce via shfl
        ull ncl = *reinterpret_cast<const ull*>(ncsh + loff);
        ull nch = *reinterpret_cast<const ull*>(ncsh + loff + hoff);
        float qv[4];
        #pragma unroll
        for (int s = 0; s < 4; ++s) {
            ull zL = add2(accL[s], ncl);
            ull zH = add2(accH[s], nch);
            ull t  = mul2(zL, zL);
            t = fma2(zH, zH, t);
            float2 f = asf2(t);
            float q = f.x + f.y;
            q += __shfl_xor_sync(0xffffffffu, q, 8);
            q += __shfl_xor_sync(0xffffffffu, q, 16);
            qv[s] = q;
        }
        __syncthreads();                    // msh/ds/ncsh mainloop reads done
        if (rq == 0)
            *reinterpret_cast<float4*>(red + rg * RSP + 32 * half + 4 * sq) =
                make_float4(qv[0], qv[1], qv[2], qv[3]);
        __syncthreads();

        if (tid < navail) {
            float sum = red[tid] + red[RSP + tid] + red[2 * RSP + tid]
                      + red[3 * RSP + tid] + red[4 * RSP + tid];
            float ll = -0.5f * sum - __ldg(g_logdet + bk) - 0.5f * (float)NDIM * LOG_2PI;
            out[((size_t)b * SEQ + s0 + tid) * KST + k] = ll;
        }
    }
}

// ---------------------------------------------------------------------------
extern "C" void kernel_launch(void* const* d_in, const int* in_sizes, int n_in,
                              void* d_out, int out_size) {
    const float* x     = (const float*)d_in[0];
    const float* mu    = (const float*)d_in[1];
    const float* sigma = (const float*)d_in[2];
    float* out = (float*)d_out;

    const int llsmem = (NDIM * MST + NDIM * DST2 + 5 * RSP + 84) * sizeof(float); // 72096 B
    cudaFuncSetAttribute(ll_kernel, cudaFuncAttributeMaxDynamicSharedMemorySize, llsmem);

    chol_inv_kernel<<<NBK, 96>>>(sigma, mu);

    dim3 grid((SEQ + ST - 1) / ST, KGRP, BATCH);   // (16, 4, 64)
    ll_kernel<<<grid, 320, llsmem>>>(x, out);
}